// round 11
// baseline (speedup 1.0000x reference)
#include <cuda_runtime.h>
#include <math.h>

// Problem constants (fixed by the dataset)
#define NNODES 49998
#define NEDGES 800000
#define DIN    128
#define DOUT   32
#define NH0    8
#define F0DIM  (NH0 * DOUT)   // 256
#define NE_PRED (NNODES / 3)  // 16666

// ---------------- scratch (device globals; no runtime allocation) -------------
__device__ float g_f0[NNODES * F0DIM];   // layer0 projected features
__device__ float g_el0[NNODES * NH0];
__device__ float g_er0[NNODES * NH0];
__device__ float g_h0[NNODES * F0DIM];   // layer0 output (post bias+ELU) = layer1 input
__device__ float g_f1[NNODES * DOUT];
__device__ float g_el1[NNODES];
__device__ float g_er1[NNODES];
__device__ float g_h1[NNODES * DOUT];    // layer1 aggregation

// CSR by dst
__device__ int   g_deg[NNODES];          // degree counters (also "cur" for fill)
__device__ int   g_rowptr[NNODES + 1];
__device__ int   g_esrc[NEDGES];         // src ids grouped by dst

// ---------------- helpers ----------------
__device__ __forceinline__ float leaky02(float v) {
    return v > 0.0f ? v : 0.2f * v;
}

__device__ __forceinline__ unsigned f2tf32(float v) {
    unsigned r;
    asm("cvt.rna.tf32.f32 %0, %1;" : "=r"(r) : "f"(v));
    return r;
}

__device__ __forceinline__ void mma_tf32(float& d0, float& d1, float& d2, float& d3,
                                         unsigned a0, unsigned a1, unsigned a2, unsigned a3,
                                         unsigned b0, unsigned b1) {
    asm volatile("mma.sync.aligned.m16n8k8.row.col.f32.tf32.tf32.f32 "
                 "{%0,%1,%2,%3}, {%4,%5,%6,%7}, {%8,%9}, {%0,%1,%2,%3};"
                 : "+f"(d0), "+f"(d1), "+f"(d2), "+f"(d3)
                 : "r"(a0), "r"(a1), "r"(a2), "r"(a3), "r"(b0), "r"(b1));
}

// ---------------- CSR build ----------------
__global__ void k_zero() {
    int i = blockIdx.x * blockDim.x + threadIdx.x;
    if (i < NNODES) g_deg[i] = 0;
}

__global__ void k_hist(const int* __restrict__ dst) {
    int e = blockIdx.x * blockDim.x + threadIdx.x;
    if (e < NEDGES) atomicAdd(&g_deg[dst[e]], 1);
}

__global__ void k_scan() {
    __shared__ int sums[1024];
    const int CH = (NNODES + 1023) / 1024;  // 49
    int t = threadIdx.x;
    int base = t * CH;
    int local = 0;
    for (int i = 0; i < CH; i++) {
        int idx = base + i;
        if (idx < NNODES) local += g_deg[idx];
    }
    sums[t] = local;
    __syncthreads();
    for (int off = 1; off < 1024; off <<= 1) {
        int v = (t >= off) ? sums[t - off] : 0;
        __syncthreads();
        sums[t] += v;
        __syncthreads();
    }
    int run = sums[t] - local;  // exclusive prefix
    for (int i = 0; i < CH; i++) {
        int idx = base + i;
        if (idx < NNODES) {
            int d = g_deg[idx];
            g_rowptr[idx] = run;
            g_deg[idx] = run;   // becomes fill cursor
            run += d;
        }
    }
    if (t == 1023) g_rowptr[NNODES] = NEDGES;
}

__global__ void k_fill(const int* __restrict__ src, const int* __restrict__ dst) {
    int e = blockIdx.x * blockDim.x + threadIdx.x;
    if (e >= NEDGES) return;
    int pos = atomicAdd(&g_deg[dst[e]], 1);
    g_esrc[pos] = src[e];
}

// ---------------- GEMM0 (tf32 MMA) + fused el0/er0 epilogue -----------------
__global__ void k_gemm0_tc(const float* __restrict__ x, const float* __restrict__ W0,
                           const float* __restrict__ al0, const float* __restrict__ ar0) {
    __shared__ unsigned xs[64][132];
    __shared__ unsigned Ws[8][264];
    __shared__ float2 als[128], ars[128];   // al0/ar0 as float2 pairs

    int row0 = blockIdx.x * 64;
    int tid = threadIdx.x;
    int w = tid >> 5, lane = tid & 31;
    int wr = w & 3, wc = w >> 2;
    int qr = lane >> 2;
    int qc = lane & 3;

    if (tid < 128) {
        als[tid] = reinterpret_cast<const float2*>(al0)[tid];
        ars[tid] = reinterpret_cast<const float2*>(ar0)[tid];
    }

    for (int m = tid; m < 64 * (DIN / 4); m += 256) {
        int r = m >> 5;
        int c4 = (m & 31) * 4;
        int gr = row0 + r;
        float4 v = (gr < NNODES) ? *reinterpret_cast<const float4*>(&x[gr * DIN + c4])
                                 : make_float4(0.f, 0.f, 0.f, 0.f);
        xs[r][c4 + 0] = f2tf32(v.x);
        xs[r][c4 + 1] = f2tf32(v.y);
        xs[r][c4 + 2] = f2tf32(v.z);
        xs[r][c4 + 3] = f2tf32(v.w);
    }

    float acc[16][4];
#pragma unroll
    for (int j = 0; j < 16; j++)
#pragma unroll
        for (int q = 0; q < 4; q++) acc[j][q] = 0.0f;

    for (int k0 = 0; k0 < DIN; k0 += 8) {
        __syncthreads();
        for (int m = tid; m < 8 * (F0DIM / 4); m += 256) {
            int kk = m >> 6;
            int c4 = (m & 63) * 4;
            float4 v = *reinterpret_cast<const float4*>(&W0[(k0 + kk) * F0DIM + c4]);
            Ws[kk][c4 + 0] = f2tf32(v.x);
            Ws[kk][c4 + 1] = f2tf32(v.y);
            Ws[kk][c4 + 2] = f2tf32(v.z);
            Ws[kk][c4 + 3] = f2tf32(v.w);
        }
        __syncthreads();

        unsigned a0 = xs[wr * 16 + qr][k0 + qc];
        unsigned a1 = xs[wr * 16 + qr + 8][k0 + qc];
        unsigned a2 = xs[wr * 16 + qr][k0 + qc + 4];
        unsigned a3 = xs[wr * 16 + qr + 8][k0 + qc + 4];

#pragma unroll
        for (int j = 0; j < 16; j++) {
            int n0 = wc * 128 + j * 8;
            unsigned b0 = Ws[qc][n0 + qr];
            unsigned b1 = Ws[qc + 4][n0 + qr];
            mma_tf32(acc[j][0], acc[j][1], acc[j][2], acc[j][3], a0, a1, a2, a3, b0, b1);
        }
    }

    // epilogue: store f0 + per-head attention dot partials
    int r1 = row0 + wr * 16 + qr;
    int r2 = r1 + 8;
    bool ok1 = r1 < NNODES, ok2 = r2 < NNODES;

    float el1p[4] = {0.f, 0.f, 0.f, 0.f}, er1p[4] = {0.f, 0.f, 0.f, 0.f};
    float el2p[4] = {0.f, 0.f, 0.f, 0.f}, er2p[4] = {0.f, 0.f, 0.f, 0.f};

#pragma unroll
    for (int j = 0; j < 16; j++) {
        int hg = j >> 2;
        int cf2 = wc * 64 + j * 4 + qc;           // float2 index of cols (c, c+1)
        float2 alv = als[cf2];
        float2 arv = ars[cf2];
        el1p[hg] += acc[j][0] * alv.x + acc[j][1] * alv.y;
        er1p[hg] += acc[j][0] * arv.x + acc[j][1] * arv.y;
        el2p[hg] += acc[j][2] * alv.x + acc[j][3] * alv.y;
        er2p[hg] += acc[j][2] * arv.x + acc[j][3] * arv.y;
        int c = wc * 128 + j * 8 + 2 * qc;
        if (ok1) *reinterpret_cast<float2*>(&g_f0[r1 * F0DIM + c]) = make_float2(acc[j][0], acc[j][1]);
        if (ok2) *reinterpret_cast<float2*>(&g_f0[r2 * F0DIM + c]) = make_float2(acc[j][2], acc[j][3]);
    }

#pragma unroll
    for (int hg = 0; hg < 4; hg++) {
        el1p[hg] += __shfl_xor_sync(0xffffffffu, el1p[hg], 1);
        el1p[hg] += __shfl_xor_sync(0xffffffffu, el1p[hg], 2);
        er1p[hg] += __shfl_xor_sync(0xffffffffu, er1p[hg], 1);
        er1p[hg] += __shfl_xor_sync(0xffffffffu, er1p[hg], 2);
        el2p[hg] += __shfl_xor_sync(0xffffffffu, el2p[hg], 1);
        el2p[hg] += __shfl_xor_sync(0xffffffffu, el2p[hg], 2);
        er2p[hg] += __shfl_xor_sync(0xffffffffu, er2p[hg], 1);
        er2p[hg] += __shfl_xor_sync(0xffffffffu, er2p[hg], 2);
    }

    if (qc == 0) {
#pragma unroll
        for (int hg = 0; hg < 4; hg++) {
            int h = wc * 4 + hg;
            if (ok1) { g_el0[r1 * NH0 + h] = el1p[hg]; g_er0[r1 * NH0 + h] = er1p[hg]; }
            if (ok2) { g_el0[r2 * NH0 + h] = el2p[hg]; g_er0[r2 * NH0 + h] = er2p[hg]; }
        }
    }
}

// ---------------- fused layer0 aggregation: 2 warps/node, column split -------
// Warp (t, half): node t, cols [half*128, half*128+128). Lane owns 1 float4.
__global__ void k_agg0(const float* __restrict__ b0) {
    int gw = (blockIdx.x * blockDim.x + threadIdx.x) >> 5;
    int lane = threadIdx.x & 31;
    int t = gw >> 1;
    int half = gw & 1;
    if (t >= NNODES) return;
    int start = g_rowptr[t], end = g_rowptr[t + 1];

    int cb = half * 128 + lane * 4;   // float4 column base
    int hc = cb >> 5;                 // head of these 4 cols
    float ert = g_er0[t * NH0 + hc];

    float ds = 0.0f;
    float4 a = make_float4(0.f, 0.f, 0.f, 0.f);

    int idx = start;
    for (; idx + 4 <= end; idx += 4) {
        int s0 = g_esrc[idx], s1 = g_esrc[idx + 1], s2 = g_esrc[idx + 2], s3 = g_esrc[idx + 3];
        float e0 = leaky02(g_el0[s0 * NH0 + hc] + ert);
        float e1 = leaky02(g_el0[s1 * NH0 + hc] + ert);
        float e2 = leaky02(g_el0[s2 * NH0 + hc] + ert);
        float e3 = leaky02(g_el0[s3 * NH0 + hc] + ert);
        float4 u = *reinterpret_cast<const float4*>(&g_f0[s0 * F0DIM + cb]);
        float4 v = *reinterpret_cast<const float4*>(&g_f0[s1 * F0DIM + cb]);
        float4 p = *reinterpret_cast<const float4*>(&g_f0[s2 * F0DIM + cb]);
        float4 q = *reinterpret_cast<const float4*>(&g_f0[s3 * F0DIM + cb]);
        float w0 = __expf(e0), w1 = __expf(e1), w2 = __expf(e2), w3 = __expf(e3);
        ds += w0 + w1 + w2 + w3;
        a.x += w0 * u.x; a.y += w0 * u.y; a.z += w0 * u.z; a.w += w0 * u.w;
        a.x += w1 * v.x; a.y += w1 * v.y; a.z += w1 * v.z; a.w += w1 * v.w;
        a.x += w2 * p.x; a.y += w2 * p.y; a.z += w2 * p.z; a.w += w2 * p.w;
        a.x += w3 * q.x; a.y += w3 * q.y; a.z += w3 * q.z; a.w += w3 * q.w;
    }
    for (; idx < end; idx++) {
        int s = g_esrc[idx];
        float w = __expf(leaky02(g_el0[s * NH0 + hc] + ert));
        float4 u = *reinterpret_cast<const float4*>(&g_f0[s * F0DIM + cb]);
        ds += w;
        a.x += w * u.x; a.y += w * u.y; a.z += w * u.z; a.w += w * u.w;
    }

    float inv = (ds > 0.0f) ? (1.0f / ds) : 0.0f;

    float4 bb = *reinterpret_cast<const float4*>(&b0[cb]);
    float o0 = a.x * inv + bb.x;
    float o1 = a.y * inv + bb.y;
    float o2 = a.z * inv + bb.z;
    float o3 = a.w * inv + bb.w;
    o0 = o0 > 0.f ? o0 : expm1f(o0);
    o1 = o1 > 0.f ? o1 : expm1f(o1);
    o2 = o2 > 0.f ? o2 : expm1f(o2);
    o3 = o3 > 0.f ? o3 : expm1f(o3);
    *reinterpret_cast<float4*>(&g_h0[t * F0DIM + cb]) = make_float4(o0, o1, o2, o3);
}

// ---------------- GEMM1 (tf32 MMA): f1 = h0 @ W1 + fused el1/er1 -------------
__global__ void k_gemm1_tc(const float* __restrict__ W1,
                           const float* __restrict__ al1, const float* __restrict__ ar1) {
    __shared__ unsigned As[64][36];
    __shared__ unsigned Wn[32][260];

    int row0 = blockIdx.x * 64;
    int tid = threadIdx.x;
    int w = tid >> 5, lane = tid & 31;
    int qr = lane >> 2, qc = lane & 3;

    // stage W1 transposed: W1[k*32+n] -> Wn[n][k]
    for (int m = tid; m < F0DIM * DOUT; m += 128) {
        int k = m >> 5, n = m & 31;
        Wn[n][k] = f2tf32(W1[m]);
    }

    float acc[4][4];
#pragma unroll
    for (int j = 0; j < 4; j++)
#pragma unroll
        for (int q = 0; q < 4; q++) acc[j][q] = 0.0f;

    for (int c0 = 0; c0 < F0DIM; c0 += 32) {
        __syncthreads();
        for (int m = tid; m < 64 * 8; m += 128) {
            int r = m >> 3;
            int f4 = (m & 7) * 4;
            int gr = row0 + r;
            float4 v = (gr < NNODES) ? *reinterpret_cast<const float4*>(&g_h0[gr * F0DIM + c0 + f4])
                                     : make_float4(0.f, 0.f, 0.f, 0.f);
            As[r][f4 + 0] = f2tf32(v.x);
            As[r][f4 + 1] = f2tf32(v.y);
            As[r][f4 + 2] = f2tf32(v.z);
            As[r][f4 + 3] = f2tf32(v.w);
        }
        __syncthreads();

#pragma unroll
        for (int s = 0; s < 4; s++) {
            int kk = s * 8;
            unsigned a0 = As[w * 16 + qr][kk + qc];
            unsigned a1 = As[w * 16 + qr + 8][kk + qc];
            unsigned a2 = As[w * 16 + qr][kk + qc + 4];
            unsigned a3 = As[w * 16 + qr + 8][kk + qc + 4];
#pragma unroll
            for (int j = 0; j < 4; j++) {
                unsigned b0 = Wn[j * 8 + qr][c0 + kk + qc];
                unsigned b1 = Wn[j * 8 + qr][c0 + kk + qc + 4];
                mma_tf32(acc[j][0], acc[j][1], acc[j][2], acc[j][3], a0, a1, a2, a3, b0, b1);
            }
        }
    }

    int r1 = row0 + w * 16 + qr;
    int r2 = r1 + 8;
    bool ok1 = r1 < NNODES, ok2 = r2 < NNODES;

    float el1p = 0.f, er1p = 0.f, el2p = 0.f, er2p = 0.f;
#pragma unroll
    for (int j = 0; j < 4; j++) {
        float2 alv = reinterpret_cast<const float2*>(al1)[j * 4 + qc];
        float2 arv = reinterpret_cast<const float2*>(ar1)[j * 4 + qc];
        el1p += acc[j][0] * alv.x + acc[j][1] * alv.y;
        er1p += acc[j][0] * arv.x + acc[j][1] * arv.y;
        el2p += acc[j][2] * alv.x + acc[j][3] * alv.y;
        er2p += acc[j][2] * arv.x + acc[j][3] * arv.y;
        int c = j * 8 + 2 * qc;
        if (ok1) *reinterpret_cast<float2*>(&g_f1[r1 * DOUT + c]) = make_float2(acc[j][0], acc[j][1]);
        if (ok2) *reinterpret_cast<float2*>(&g_f1[r2 * DOUT + c]) = make_float2(acc[j][2], acc[j][3]);
    }

    el1p += __shfl_xor_sync(0xffffffffu, el1p, 1);
    el1p += __shfl_xor_sync(0xffffffffu, el1p, 2);
    er1p += __shfl_xor_sync(0xffffffffu, er1p, 1);
    er1p += __shfl_xor_sync(0xffffffffu, er1p, 2);
    el2p += __shfl_xor_sync(0xffffffffu, el2p, 1);
    el2p += __shfl_xor_sync(0xffffffffu, el2p, 2);
    er2p += __shfl_xor_sync(0xffffffffu, er2p, 1);
    er2p += __shfl_xor_sync(0xffffffffu, er2p, 2);

    if (qc == 0) {
        if (ok1) { g_el1[r1] = el1p; g_er1[r1] = er1p; }
        if (ok2) { g_el1[r2] = el2p; g_er1[r2] = er2p; }
    }
}

// ---------------- fused layer1 aggregation (H1 = 1), unroll 4 ----------------
__global__ void k_agg1() {
    int gw = (blockIdx.x * blockDim.x + threadIdx.x) >> 5;
    int lane = threadIdx.x & 31;
    if (gw >= NNODES) return;
    int t = gw;
    int start = g_rowptr[t], end = g_rowptr[t + 1];
    float ert = g_er1[t];

    float ds = 0.0f;
    float acc = 0.0f;

    int idx = start;
    for (; idx + 4 <= end; idx += 4) {
        int s0 = g_esrc[idx], s1 = g_esrc[idx + 1], s2 = g_esrc[idx + 2], s3 = g_esrc[idx + 3];
        float e0 = leaky02(g_el1[s0] + ert);
        float e1 = leaky02(g_el1[s1] + ert);
        float e2 = leaky02(g_el1[s2] + ert);
        float e3 = leaky02(g_el1[s3] + ert);
        float f0v = g_f1[s0 * DOUT + lane];
        float f1v = g_f1[s1 * DOUT + lane];
        float f2v = g_f1[s2 * DOUT + lane];
        float f3v = g_f1[s3 * DOUT + lane];
        float w0 = __expf(e0), w1 = __expf(e1), w2 = __expf(e2), w3 = __expf(e3);
        ds += w0 + w1 + w2 + w3;
        acc += w0 * f0v + w1 * f1v + w2 * f2v + w3 * f3v;
    }
    for (; idx < end; idx++) {
        int s = g_esrc[idx];
        float w = __expf(leaky02(g_el1[s] + ert));
        ds += w;
        acc += w * g_f1[s * DOUT + lane];
    }

    float inv = (ds > 0.0f) ? (1.0f / ds) : 0.0f;
    g_h1[t * DOUT + lane] = acc * inv;
}

// ---------------- link predictor ----------------
__global__ void k_pred(const float* __restrict__ b1,
                       const float* __restrict__ P1, const float* __restrict__ pb1,
                       const float* __restrict__ P2, const float* __restrict__ pb2,
                       const float* __restrict__ P3, const float* __restrict__ pb3,
                       float* __restrict__ out) {
    int tid = blockIdx.x * blockDim.x + threadIdx.x;
    int w = tid >> 5;
    int lane = tid & 31;
    if (w >= 2 * NE_PRED) return;

    int si = (w < NE_PRED) ? w : (w - NE_PRED);
    int di = NE_PRED + w;   // pos: [NE,2NE); neg: [2NE,3NE)

    float bz = b1[lane];
    float z = (g_h1[si * DOUT + lane] + bz) * (g_h1[di * DOUT + lane] + bz);

    float y = pb1[lane];
#pragma unroll
    for (int k = 0; k < DOUT; k++)
        y += __shfl_sync(0xffffffffu, z, k) * P1[k * DOUT + lane];
    y = fmaxf(y, 0.0f);

    float y2 = pb2[lane];
#pragma unroll
    for (int k = 0; k < DOUT; k++)
        y2 += __shfl_sync(0xffffffffu, y, k) * P2[k * DOUT + lane];
    y2 = fmaxf(y2, 0.0f);

    float o = y2 * P3[lane];
#pragma unroll
    for (int off = 16; off > 0; off >>= 1)
        o += __shfl_xor_sync(0xffffffffu, o, off);
    if (lane == 0) out[w] = o + pb3[0];
}

// ---------------- launcher ----------------
extern "C" void kernel_launch(void* const* d_in, const int* in_sizes, int n_in,
                              void* d_out, int out_size) {
    const float* x   = (const float*)d_in[0];
    const int*   src = (const int*)d_in[1];
    const int*   dst = (const int*)d_in[2];
    // d_in[3] = neg_sample_ratio (fixed = 1)
    const float* W0  = (const float*)d_in[4];
    const float* al0 = (const float*)d_in[5];
    const float* ar0 = (const float*)d_in[6];
    const float* b0  = (const float*)d_in[7];
    const float* W1  = (const float*)d_in[8];
    const float* al1 = (const float*)d_in[9];
    const float* ar1 = (const float*)d_in[10];
    const float* b1  = (const float*)d_in[11];
    const float* P1  = (const float*)d_in[12];
    const float* pb1 = (const float*)d_in[13];
    const float* P2  = (const float*)d_in[14];
    const float* pb2 = (const float*)d_in[15];
    const float* P3  = (const float*)d_in[16];
    const float* pb3 = (const float*)d_in[17];
    float* out = (float*)d_out;

    // Side stream: CSR build runs parallel to GEMM0 (independent of it).
    // Created fresh each call (host-side only; kernel_launch is invoked only a
    // handful of times — correctness + capture — so not destroying them avoids
    // any destroy-during-capture hazard).
    cudaStream_t s2;
    cudaEvent_t eFork, eJoin;
    cudaStreamCreateWithFlags(&s2, cudaStreamNonBlocking);
    cudaEventCreateWithFlags(&eFork, cudaEventDisableTiming);
    cudaEventCreateWithFlags(&eJoin, cudaEventDisableTiming);

    cudaEventRecord(eFork, 0);
    cudaStreamWaitEvent(s2, eFork, 0);

    // CSR chain on side stream
    k_zero<<<(NNODES + 255) / 256, 256, 0, s2>>>();
    k_hist<<<(NEDGES + 255) / 256, 256, 0, s2>>>(dst);
    k_scan<<<1, 1024, 0, s2>>>();
    k_fill<<<(NEDGES + 255) / 256, 256, 0, s2>>>(src, dst);
    cudaEventRecord(eJoin, s2);

    // GEMM0 on main stream, concurrent with CSR build
    k_gemm0_tc<<<(NNODES + 63) / 64, 256>>>(x, W0, al0, ar0);

    // join: agg0 needs both CSR and f0/el0/er0
    cudaStreamWaitEvent(0, eJoin, 0);
    k_agg0<<<(2 * NNODES + 7) / 8, 256>>>(b0);

    // Layer 1
    k_gemm1_tc<<<(NNODES + 63) / 64, 128>>>(W1, al1, ar1);
    k_agg1<<<(NNODES + 7) / 8, 256>>>();

    // Predictor
    k_pred<<<(2 * NE_PRED * 32 + 255) / 256, 256>>>(b1, P1, pb1, P2, pb2, P3, pb3, out);
}

// round 15
// speedup vs baseline: 1.0937x; 1.0937x over previous
#include <cuda_runtime.h>
#include <cuda_fp16.h>
#include <math.h>

// Problem constants (fixed by the dataset)
#define NNODES 49998
#define NEDGES 800000
#define DIN    128
#define DOUT   32
#define NH0    8
#define F0DIM  (NH0 * DOUT)   // 256
#define NE_PRED (NNODES / 3)  // 16666

// ---------------- scratch (device globals; no runtime allocation) -------------
__device__ __half g_f0h[NNODES * F0DIM]; // layer0 projected features (fp16 for gather BW)
__device__ float g_el0[NNODES * NH0];
__device__ float g_er0[NNODES * NH0];
__device__ float g_h0[NNODES * F0DIM];   // layer0 output (post bias+ELU) = layer1 input
__device__ float g_f1[NNODES * DOUT];
__device__ float g_el1[NNODES];
__device__ float g_er1[NNODES];
__device__ float g_h1[NNODES * DOUT];    // layer1 aggregation

// CSR by dst
__device__ int   g_deg[NNODES];          // degree counters (also "cur" for fill)
__device__ int   g_rowptr[NNODES + 1];
__device__ int   g_esrc[NEDGES];         // src ids grouped by dst

// ---------------- helpers ----------------
__device__ __forceinline__ float leaky02(float v) {
    return v > 0.0f ? v : 0.2f * v;
}

__device__ __forceinline__ unsigned f2tf32(float v) {
    unsigned r;
    asm("cvt.rna.tf32.f32 %0, %1;" : "=r"(r) : "f"(v));
    return r;
}

__device__ __forceinline__ void mma_tf32(float& d0, float& d1, float& d2, float& d3,
                                         unsigned a0, unsigned a1, unsigned a2, unsigned a3,
                                         unsigned b0, unsigned b1) {
    asm volatile("mma.sync.aligned.m16n8k8.row.col.f32.tf32.tf32.f32 "
                 "{%0,%1,%2,%3}, {%4,%5,%6,%7}, {%8,%9}, {%0,%1,%2,%3};"
                 : "+f"(d0), "+f"(d1), "+f"(d2), "+f"(d3)
                 : "r"(a0), "r"(a1), "r"(a2), "r"(a3), "r"(b0), "r"(b1));
}

// ---------------- CSR build ----------------
__global__ void k_zero() {
    int i = blockIdx.x * blockDim.x + threadIdx.x;
    if (i < NNODES) g_deg[i] = 0;
}

__global__ void k_hist(const int* __restrict__ dst) {
    int e = blockIdx.x * blockDim.x + threadIdx.x;
    if (e < NEDGES) atomicAdd(&g_deg[dst[e]], 1);
}

__global__ void k_scan() {
    __shared__ int sums[1024];
    const int CH = (NNODES + 1023) / 1024;  // 49
    int t = threadIdx.x;
    int base = t * CH;
    int local = 0;
    for (int i = 0; i < CH; i++) {
        int idx = base + i;
        if (idx < NNODES) local += g_deg[idx];
    }
    sums[t] = local;
    __syncthreads();
    for (int off = 1; off < 1024; off <<= 1) {
        int v = (t >= off) ? sums[t - off] : 0;
        __syncthreads();
        sums[t] += v;
        __syncthreads();
    }
    int run = sums[t] - local;  // exclusive prefix
    for (int i = 0; i < CH; i++) {
        int idx = base + i;
        if (idx < NNODES) {
            int d = g_deg[idx];
            g_rowptr[idx] = run;
            g_deg[idx] = run;   // becomes fill cursor
            run += d;
        }
    }
    if (t == 1023) g_rowptr[NNODES] = NEDGES;
}

__global__ void k_fill(const int* __restrict__ src, const int* __restrict__ dst) {
    int e = blockIdx.x * blockDim.x + threadIdx.x;
    if (e >= NEDGES) return;
    int pos = atomicAdd(&g_deg[dst[e]], 1);
    g_esrc[pos] = src[e];
}

// ---------------- GEMM0 (tf32 MMA) + fused el0/er0 epilogue -----------------
// Block: 256 threads = 8 warps. Tile M=64, N=256. Warp w: rows (w%4)*16, cols (w/4)*128.
// f0 stored as fp16 (only consumer is agg0's gather); el0/er0 from fp32 accumulators.
__global__ void k_gemm0_tc(const float* __restrict__ x, const float* __restrict__ W0,
                           const float* __restrict__ al0, const float* __restrict__ ar0) {
    __shared__ unsigned xs[64][132];
    __shared__ unsigned Ws[8][264];
    __shared__ float2 als[128], ars[128];   // al0/ar0 as float2 pairs

    int row0 = blockIdx.x * 64;
    int tid = threadIdx.x;
    int w = tid >> 5, lane = tid & 31;
    int wr = w & 3, wc = w >> 5 == 0 ? (w >> 2) : (w >> 2);  // w/4
    wc = w >> 2;
    int qr = lane >> 2;
    int qc = lane & 3;

    if (tid < 128) {
        als[tid] = reinterpret_cast<const float2*>(al0)[tid];
        ars[tid] = reinterpret_cast<const float2*>(ar0)[tid];
    }

    for (int m = tid; m < 64 * (DIN / 4); m += 256) {
        int r = m >> 5;
        int c4 = (m & 31) * 4;
        int gr = row0 + r;
        float4 v = (gr < NNODES) ? *reinterpret_cast<const float4*>(&x[gr * DIN + c4])
                                 : make_float4(0.f, 0.f, 0.f, 0.f);
        xs[r][c4 + 0] = f2tf32(v.x);
        xs[r][c4 + 1] = f2tf32(v.y);
        xs[r][c4 + 2] = f2tf32(v.z);
        xs[r][c4 + 3] = f2tf32(v.w);
    }

    float acc[16][4];
#pragma unroll
    for (int j = 0; j < 16; j++)
#pragma unroll
        for (int q = 0; q < 4; q++) acc[j][q] = 0.0f;

    for (int k0 = 0; k0 < DIN; k0 += 8) {
        __syncthreads();
        for (int m = tid; m < 8 * (F0DIM / 4); m += 256) {
            int kk = m >> 6;
            int c4 = (m & 63) * 4;
            float4 v = *reinterpret_cast<const float4*>(&W0[(k0 + kk) * F0DIM + c4]);
            Ws[kk][c4 + 0] = f2tf32(v.x);
            Ws[kk][c4 + 1] = f2tf32(v.y);
            Ws[kk][c4 + 2] = f2tf32(v.z);
            Ws[kk][c4 + 3] = f2tf32(v.w);
        }
        __syncthreads();

        unsigned a0 = xs[wr * 16 + qr][k0 + qc];
        unsigned a1 = xs[wr * 16 + qr + 8][k0 + qc];
        unsigned a2 = xs[wr * 16 + qr][k0 + qc + 4];
        unsigned a3 = xs[wr * 16 + qr + 8][k0 + qc + 4];

#pragma unroll
        for (int j = 0; j < 16; j++) {
            int n0 = wc * 128 + j * 8;
            unsigned b0 = Ws[qc][n0 + qr];
            unsigned b1 = Ws[qc + 4][n0 + qr];
            mma_tf32(acc[j][0], acc[j][1], acc[j][2], acc[j][3], a0, a1, a2, a3, b0, b1);
        }
    }

    // epilogue: store f0 (fp16) + per-head attention dot partials (fp32)
    int r1 = row0 + wr * 16 + qr;
    int r2 = r1 + 8;
    bool ok1 = r1 < NNODES, ok2 = r2 < NNODES;

    float el1p[4] = {0.f, 0.f, 0.f, 0.f}, er1p[4] = {0.f, 0.f, 0.f, 0.f};
    float el2p[4] = {0.f, 0.f, 0.f, 0.f}, er2p[4] = {0.f, 0.f, 0.f, 0.f};

#pragma unroll
    for (int j = 0; j < 16; j++) {
        int hg = j >> 2;
        int cf2 = wc * 64 + j * 4 + qc;           // float2 index of cols (c, c+1)
        float2 alv = als[cf2];
        float2 arv = ars[cf2];
        el1p[hg] += acc[j][0] * alv.x + acc[j][1] * alv.y;
        er1p[hg] += acc[j][0] * arv.x + acc[j][1] * arv.y;
        el2p[hg] += acc[j][2] * alv.x + acc[j][3] * alv.y;
        er2p[hg] += acc[j][2] * arv.x + acc[j][3] * arv.y;
        int c = wc * 128 + j * 8 + 2 * qc;
        if (ok1) *reinterpret_cast<__half2*>(&g_f0h[r1 * F0DIM + c]) =
                     __floats2half2_rn(acc[j][0], acc[j][1]);
        if (ok2) *reinterpret_cast<__half2*>(&g_f0h[r2 * F0DIM + c]) =
                     __floats2half2_rn(acc[j][2], acc[j][3]);
    }

#pragma unroll
    for (int hg = 0; hg < 4; hg++) {
        el1p[hg] += __shfl_xor_sync(0xffffffffu, el1p[hg], 1);
        el1p[hg] += __shfl_xor_sync(0xffffffffu, el1p[hg], 2);
        er1p[hg] += __shfl_xor_sync(0xffffffffu, er1p[hg], 1);
        er1p[hg] += __shfl_xor_sync(0xffffffffu, er1p[hg], 2);
        el2p[hg] += __shfl_xor_sync(0xffffffffu, el2p[hg], 1);
        el2p[hg] += __shfl_xor_sync(0xffffffffu, el2p[hg], 2);
        er2p[hg] += __shfl_xor_sync(0xffffffffu, er2p[hg], 1);
        er2p[hg] += __shfl_xor_sync(0xffffffffu, er2p[hg], 2);
    }

    if (qc == 0) {
#pragma unroll
        for (int hg = 0; hg < 4; hg++) {
            int h = wc * 4 + hg;
            if (ok1) { g_el0[r1 * NH0 + h] = el1p[hg]; g_er0[r1 * NH0 + h] = er1p[hg]; }
            if (ok2) { g_el0[r2 * NH0 + h] = el2p[hg]; g_er0[r2 * NH0 + h] = er2p[hg]; }
        }
    }
}

// ---------------- fused layer0 aggregation: ONE edge sweep, fp16 gather ------
// One warp per node. Lane owns cols [lane*8, lane*8+8) = one uint4 (8 halves).
__global__ void k_agg0(const float* __restrict__ b0) {
    int gw = (blockIdx.x * blockDim.x + threadIdx.x) >> 5;
    int lane = threadIdx.x & 31;
    if (gw >= NNODES) return;
    int t = gw;
    int start = g_rowptr[t], end = g_rowptr[t + 1];

    int hc = lane >> 2;
    int cb = lane * 8;
    float ert = g_er0[t * NH0 + hc];

    float ds = 0.0f;
    float4 a0 = make_float4(0.f, 0.f, 0.f, 0.f);
    float4 a1 = make_float4(0.f, 0.f, 0.f, 0.f);

#define ACC_EDGE(Wt, HV)                                                     \
    do {                                                                     \
        float2 p0 = __half22float2(*reinterpret_cast<const __half2*>(&(HV).x)); \
        float2 p1 = __half22float2(*reinterpret_cast<const __half2*>(&(HV).y)); \
        float2 p2 = __half22float2(*reinterpret_cast<const __half2*>(&(HV).z)); \
        float2 p3 = __half22float2(*reinterpret_cast<const __half2*>(&(HV).w)); \
        a0.x += (Wt) * p0.x; a0.y += (Wt) * p0.y;                            \
        a0.z += (Wt) * p1.x; a0.w += (Wt) * p1.y;                            \
        a1.x += (Wt) * p2.x; a1.y += (Wt) * p2.y;                            \
        a1.z += (Wt) * p3.x; a1.w += (Wt) * p3.y;                            \
    } while (0)

    int idx = start;
    for (; idx + 4 <= end; idx += 4) {
        int s0 = g_esrc[idx], s1 = g_esrc[idx + 1], s2 = g_esrc[idx + 2], s3 = g_esrc[idx + 3];
        float e0 = leaky02(g_el0[s0 * NH0 + hc] + ert);
        float e1 = leaky02(g_el0[s1 * NH0 + hc] + ert);
        float e2 = leaky02(g_el0[s2 * NH0 + hc] + ert);
        float e3 = leaky02(g_el0[s3 * NH0 + hc] + ert);
        uint4 hv0 = *reinterpret_cast<const uint4*>(&g_f0h[s0 * F0DIM + cb]);
        uint4 hv1 = *reinterpret_cast<const uint4*>(&g_f0h[s1 * F0DIM + cb]);
        uint4 hv2 = *reinterpret_cast<const uint4*>(&g_f0h[s2 * F0DIM + cb]);
        uint4 hv3 = *reinterpret_cast<const uint4*>(&g_f0h[s3 * F0DIM + cb]);
        float w0 = __expf(e0), w1 = __expf(e1), w2 = __expf(e2), w3 = __expf(e3);
        ds += w0 + w1 + w2 + w3;
        ACC_EDGE(w0, hv0);
        ACC_EDGE(w1, hv1);
        ACC_EDGE(w2, hv2);
        ACC_EDGE(w3, hv3);
    }
    for (; idx < end; idx++) {
        int s = g_esrc[idx];
        float w = __expf(leaky02(g_el0[s * NH0 + hc] + ert));
        uint4 hv = *reinterpret_cast<const uint4*>(&g_f0h[s * F0DIM + cb]);
        ds += w;
        ACC_EDGE(w, hv);
    }
#undef ACC_EDGE

    float inv = (ds > 0.0f) ? (1.0f / ds) : 0.0f;

    float4 bb0 = *reinterpret_cast<const float4*>(&b0[cb]);
    float4 bb1 = *reinterpret_cast<const float4*>(&b0[cb + 4]);
    float o[8] = {a0.x * inv + bb0.x, a0.y * inv + bb0.y, a0.z * inv + bb0.z, a0.w * inv + bb0.w,
                  a1.x * inv + bb1.x, a1.y * inv + bb1.y, a1.z * inv + bb1.z, a1.w * inv + bb1.w};
#pragma unroll
    for (int j = 0; j < 8; j++) o[j] = o[j] > 0.0f ? o[j] : expm1f(o[j]);
    *reinterpret_cast<float4*>(&g_h0[t * F0DIM + cb])     = make_float4(o[0], o[1], o[2], o[3]);
    *reinterpret_cast<float4*>(&g_h0[t * F0DIM + cb + 4]) = make_float4(o[4], o[5], o[6], o[7]);
}

// ---------------- GEMM1 (tf32 MMA): f1 = h0 @ W1 + fused el1/er1 -------------
__global__ void k_gemm1_tc(const float* __restrict__ W1,
                           const float* __restrict__ al1, const float* __restrict__ ar1) {
    __shared__ unsigned As[64][36];
    __shared__ unsigned Wn[32][260];

    int row0 = blockIdx.x * 64;
    int tid = threadIdx.x;
    int w = tid >> 5, lane = tid & 31;
    int qr = lane >> 2, qc = lane & 3;

    // stage W1 transposed: W1[k*32+n] -> Wn[n][k]
    for (int m = tid; m < F0DIM * DOUT; m += 128) {
        int k = m >> 5, n = m & 31;
        Wn[n][k] = f2tf32(W1[m]);
    }

    float acc[4][4];
#pragma unroll
    for (int j = 0; j < 4; j++)
#pragma unroll
        for (int q = 0; q < 4; q++) acc[j][q] = 0.0f;

    for (int c0 = 0; c0 < F0DIM; c0 += 32) {
        __syncthreads();
        for (int m = tid; m < 64 * 8; m += 128) {
            int r = m >> 3;
            int f4 = (m & 7) * 4;
            int gr = row0 + r;
            float4 v = (gr < NNODES) ? *reinterpret_cast<const float4*>(&g_h0[gr * F0DIM + c0 + f4])
                                     : make_float4(0.f, 0.f, 0.f, 0.f);
            As[r][f4 + 0] = f2tf32(v.x);
            As[r][f4 + 1] = f2tf32(v.y);
            As[r][f4 + 2] = f2tf32(v.z);
            As[r][f4 + 3] = f2tf32(v.w);
        }
        __syncthreads();

#pragma unroll
        for (int s = 0; s < 4; s++) {
            int kk = s * 8;
            unsigned a0 = As[w * 16 + qr][kk + qc];
            unsigned a1 = As[w * 16 + qr + 8][kk + qc];
            unsigned a2 = As[w * 16 + qr][kk + qc + 4];
            unsigned a3 = As[w * 16 + qr + 8][kk + qc + 4];
#pragma unroll
            for (int j = 0; j < 4; j++) {
                unsigned b0 = Wn[j * 8 + qr][c0 + kk + qc];
                unsigned b1 = Wn[j * 8 + qr][c0 + kk + qc + 4];
                mma_tf32(acc[j][0], acc[j][1], acc[j][2], acc[j][3], a0, a1, a2, a3, b0, b1);
            }
        }
    }

    int r1 = row0 + w * 16 + qr;
    int r2 = r1 + 8;
    bool ok1 = r1 < NNODES, ok2 = r2 < NNODES;

    float el1p = 0.f, er1p = 0.f, el2p = 0.f, er2p = 0.f;
#pragma unroll
    for (int j = 0; j < 4; j++) {
        float2 alv = reinterpret_cast<const float2*>(al1)[j * 4 + qc];
        float2 arv = reinterpret_cast<const float2*>(ar1)[j * 4 + qc];
        el1p += acc[j][0] * alv.x + acc[j][1] * alv.y;
        er1p += acc[j][0] * arv.x + acc[j][1] * arv.y;
        el2p += acc[j][2] * alv.x + acc[j][3] * alv.y;
        er2p += acc[j][2] * arv.x + acc[j][3] * arv.y;
        int c = j * 8 + 2 * qc;
        if (ok1) *reinterpret_cast<float2*>(&g_f1[r1 * DOUT + c]) = make_float2(acc[j][0], acc[j][1]);
        if (ok2) *reinterpret_cast<float2*>(&g_f1[r2 * DOUT + c]) = make_float2(acc[j][2], acc[j][3]);
    }

    el1p += __shfl_xor_sync(0xffffffffu, el1p, 1);
    el1p += __shfl_xor_sync(0xffffffffu, el1p, 2);
    er1p += __shfl_xor_sync(0xffffffffu, er1p, 1);
    er1p += __shfl_xor_sync(0xffffffffu, er1p, 2);
    el2p += __shfl_xor_sync(0xffffffffu, el2p, 1);
    el2p += __shfl_xor_sync(0xffffffffu, el2p, 2);
    er2p += __shfl_xor_sync(0xffffffffu, er2p, 1);
    er2p += __shfl_xor_sync(0xffffffffu, er2p, 2);

    if (qc == 0) {
        if (ok1) { g_el1[r1] = el1p; g_er1[r1] = er1p; }
        if (ok2) { g_el1[r2] = el2p; g_er1[r2] = er2p; }
    }
}

// ---------------- fused layer1 aggregation (H1 = 1), unroll 4 ----------------
__global__ void k_agg1() {
    int gw = (blockIdx.x * blockDim.x + threadIdx.x) >> 5;
    int lane = threadIdx.x & 31;
    if (gw >= NNODES) return;
    int t = gw;
    int start = g_rowptr[t], end = g_rowptr[t + 1];
    float ert = g_er1[t];

    float ds = 0.0f;
    float acc = 0.0f;

    int idx = start;
    for (; idx + 4 <= end; idx += 4) {
        int s0 = g_esrc[idx], s1 = g_esrc[idx + 1], s2 = g_esrc[idx + 2], s3 = g_esrc[idx + 3];
        float e0 = leaky02(g_el1[s0] + ert);
        float e1 = leaky02(g_el1[s1] + ert);
        float e2 = leaky02(g_el1[s2] + ert);
        float e3 = leaky02(g_el1[s3] + ert);
        float f0v = g_f1[s0 * DOUT + lane];
        float f1v = g_f1[s1 * DOUT + lane];
        float f2v = g_f1[s2 * DOUT + lane];
        float f3v = g_f1[s3 * DOUT + lane];
        float w0 = __expf(e0), w1 = __expf(e1), w2 = __expf(e2), w3 = __expf(e3);
        ds += w0 + w1 + w2 + w3;
        acc += w0 * f0v + w1 * f1v + w2 * f2v + w3 * f3v;
    }
    for (; idx < end; idx++) {
        int s = g_esrc[idx];
        float w = __expf(leaky02(g_el1[s] + ert));
        ds += w;
        acc += w * g_f1[s * DOUT + lane];
    }

    float inv = (ds > 0.0f) ? (1.0f / ds) : 0.0f;
    g_h1[t * DOUT + lane] = acc * inv;
}

// ---------------- link predictor ----------------
__global__ void k_pred(const float* __restrict__ b1,
                       const float* __restrict__ P1, const float* __restrict__ pb1,
                       const float* __restrict__ P2, const float* __restrict__ pb2,
                       const float* __restrict__ P3, const float* __restrict__ pb3,
                       float* __restrict__ out) {
    int tid = blockIdx.x * blockDim.x + threadIdx.x;
    int w = tid >> 5;
    int lane = tid & 31;
    if (w >= 2 * NE_PRED) return;

    int si = (w < NE_PRED) ? w : (w - NE_PRED);
    int di = NE_PRED + w;   // pos: [NE,2NE); neg: [2NE,3NE)

    float bz = b1[lane];
    float z = (g_h1[si * DOUT + lane] + bz) * (g_h1[di * DOUT + lane] + bz);

    float y = pb1[lane];
#pragma unroll
    for (int k = 0; k < DOUT; k++)
        y += __shfl_sync(0xffffffffu, z, k) * P1[k * DOUT + lane];
    y = fmaxf(y, 0.0f);

    float y2 = pb2[lane];
#pragma unroll
    for (int k = 0; k < DOUT; k++)
        y2 += __shfl_sync(0xffffffffu, y, k) * P2[k * DOUT + lane];
    y2 = fmaxf(y2, 0.0f);

    float o = y2 * P3[lane];
#pragma unroll
    for (int off = 16; off > 0; off >>= 1)
        o += __shfl_xor_sync(0xffffffffu, o, off);
    if (lane == 0) out[w] = o + pb3[0];
}

// ---------------- launcher ----------------
extern "C" void kernel_launch(void* const* d_in, const int* in_sizes, int n_in,
                              void* d_out, int out_size) {
    const float* x   = (const float*)d_in[0];
    const int*   src = (const int*)d_in[1];
    const int*   dst = (const int*)d_in[2];
    // d_in[3] = neg_sample_ratio (fixed = 1)
    const float* W0  = (const float*)d_in[4];
    const float* al0 = (const float*)d_in[5];
    const float* ar0 = (const float*)d_in[6];
    const float* b0  = (const float*)d_in[7];
    const float* W1  = (const float*)d_in[8];
    const float* al1 = (const float*)d_in[9];
    const float* ar1 = (const float*)d_in[10];
    const float* b1  = (const float*)d_in[11];
    const float* P1  = (const float*)d_in[12];
    const float* pb1 = (const float*)d_in[13];
    const float* P2  = (const float*)d_in[14];
    const float* pb2 = (const float*)d_in[15];
    const float* P3  = (const float*)d_in[16];
    const float* pb3 = (const float*)d_in[17];
    float* out = (float*)d_out;

    // CSR build (serial; the R8 stream-fork experiment regressed)
    k_zero<<<(NNODES + 255) / 256, 256>>>();
    k_hist<<<(NEDGES + 255) / 256, 256>>>(dst);
    k_scan<<<1, 1024>>>();
    k_fill<<<(NEDGES + 255) / 256, 256>>>(src, dst);

    // Layer 0
    k_gemm0_tc<<<(NNODES + 63) / 64, 256>>>(x, W0, al0, ar0);
    k_agg0<<<(NNODES + 7) / 8, 256>>>(b0);

    // Layer 1
    k_gemm1_tc<<<(NNODES + 63) / 64, 128>>>(W1, al1, ar1);
    k_agg1<<<(NNODES + 7) / 8, 256>>>();

    // Predictor
    k_pred<<<(2 * NE_PRED * 32 + 255) / 256, 256>>>(b1, P1, pb1, P2, pb2, P3, pb3, out);
}